// round 2
// baseline (speedup 1.0000x reference)
#include <cuda_runtime.h>
#include <math.h>

#define NM 1024
#define H 256
#define W 256
#define HW (H * W)
#define TOTAL ((size_t)NM * HW)

#define PRED_IOU_THRESH 0.88f
#define STABILITY_THRESH 0.95f
#define BOX_NMS_THRESH 0.7f

// Per-mask scratch (allocation-free: __device__ globals)
__device__ float4 g_boxes[NM];   // xyxy inclusive, zeros if empty
__device__ float  g_score[NM];   // iou_pred if valid else -inf
__device__ float  g_gated[NM];   // iou_pred if kept else 0

// ---------------------------------------------------------------------------
// Pass 1: per-mask stats. One block per mask, 256 threads, float4 loads.
// Computes hi = count(logit>1), lo = count(logit>-1), bbox of (logit>0).
// ---------------------------------------------------------------------------
__global__ void __launch_bounds__(256) stats_kernel(const float* __restrict__ logits,
                                                    const float* __restrict__ iou_preds) {
    const int m = blockIdx.x;
    const int tid = threadIdx.x;
    const float4* base = reinterpret_cast<const float4*>(logits) + (size_t)m * (HW / 4);

    int hi = 0, lo = 0;
    int minr = H, maxr = -1, minc = W, maxc = -1;

#pragma unroll 4
    for (int it = 0; it < 64; ++it) {
        int v4idx = it * 256 + tid;          // float4 index within mask
        float4 v = base[v4idx];
        int fidx = v4idx * 4;                // float index
        int row = fidx >> 8;                 // W=256
        int col = fidx & 255;

        hi += (v.x > 1.0f) + (v.y > 1.0f) + (v.z > 1.0f) + (v.w > 1.0f);
        lo += (v.x > -1.0f) + (v.y > -1.0f) + (v.z > -1.0f) + (v.w > -1.0f);

        bool any = false;
        if (v.x > 0.0f) { minc = min(minc, col);     maxc = max(maxc, col);     any = true; }
        if (v.y > 0.0f) { minc = min(minc, col + 1); maxc = max(maxc, col + 1); any = true; }
        if (v.z > 0.0f) { minc = min(minc, col + 2); maxc = max(maxc, col + 2); any = true; }
        if (v.w > 0.0f) { minc = min(minc, col + 3); maxc = max(maxc, col + 3); any = true; }
        if (any) { minr = min(minr, row); maxr = max(maxr, row); }
    }

    // warp reduce
#pragma unroll
    for (int off = 16; off > 0; off >>= 1) {
        hi   += __shfl_down_sync(0xffffffffu, hi, off);
        lo   += __shfl_down_sync(0xffffffffu, lo, off);
        minr = min(minr, __shfl_down_sync(0xffffffffu, minr, off));
        maxr = max(maxr, __shfl_down_sync(0xffffffffu, maxr, off));
        minc = min(minc, __shfl_down_sync(0xffffffffu, minc, off));
        maxc = max(maxc, __shfl_down_sync(0xffffffffu, maxc, off));
    }

    __shared__ int sh[8][6];
    int warp = tid >> 5;
    if ((tid & 31) == 0) {
        sh[warp][0] = hi;  sh[warp][1] = lo;
        sh[warp][2] = minr; sh[warp][3] = maxr;
        sh[warp][4] = minc; sh[warp][5] = maxc;
    }
    __syncthreads();

    if (tid == 0) {
#pragma unroll
        for (int wq = 1; wq < 8; ++wq) {
            hi += sh[wq][0]; lo += sh[wq][1];
            minr = min(minr, sh[wq][2]); maxr = max(maxr, sh[wq][3]);
            minc = min(minc, sh[wq][4]); maxc = max(maxc, sh[wq][5]);
        }
        float stability = (float)hi / fmaxf((float)lo, 1.0f);
        float iou = iou_preds[m];
        bool valid = (iou > PRED_IOU_THRESH) && (stability >= STABILITY_THRESH);
        bool empty = (maxr < 0);
        float4 box;
        if (empty) box = make_float4(0.f, 0.f, 0.f, 0.f);
        else       box = make_float4((float)minc, (float)minr, (float)maxc, (float)maxr);
        g_boxes[m] = box;
        g_score[m] = valid ? iou : -INFINITY;
    }
}

// ---------------------------------------------------------------------------
// NMS: single block, 1024 threads. Bitonic sort by (score desc, idx asc)
// (stable-argsort replica), greedy suppression, scatter keep & write tail.
// ---------------------------------------------------------------------------
__global__ void __launch_bounds__(1024) nms_kernel(const float* __restrict__ iou_preds,
                                                   float* __restrict__ dout,
                                                   long long out_size) {
    __shared__ float  ss[NM];
    __shared__ int    si[NM];
    __shared__ float4 sb[NM];
    __shared__ int    sk[NM];
    __shared__ int    s_nv;

    const int t = threadIdx.x;
    ss[t] = g_score[t];
    si[t] = t;
    if (t == 0) s_nv = 0;
    __syncthreads();

    // bitonic sort: "less" = comes first = (score greater) or (tie, idx smaller)
    for (int k = 2; k <= NM; k <<= 1) {
        for (int j = k >> 1; j > 0; j >>= 1) {
            int ixj = t ^ j;
            if (ixj > t) {
                float sa = ss[t], sb_ = ss[ixj];
                int   ia = si[t], ib = si[ixj];
                bool less = (sa > sb_) || (sa == sb_ && ia < ib);
                bool dir = ((t & k) == 0);
                if (less != dir) {
                    ss[t] = sb_; ss[ixj] = sa;
                    si[t] = ib;  si[ixj] = ia;
                }
            }
            __syncthreads();
        }
    }

    sb[t] = g_boxes[si[t]];
    int keep0 = (ss[t] > -INFINITY) ? 1 : 0;
    sk[t] = keep0;
    atomicAdd(&s_nv, keep0);
    __syncthreads();

    const int nvalid = s_nv;
    const float4 bt = sb[t];
    const float area_t = fmaxf(bt.z - bt.x, 0.0f) * fmaxf(bt.w - bt.y, 0.0f);

    for (int i = 0; i < nvalid; ++i) {
        if (sk[i]) {
            float4 bi = sb[i];
            float x0 = fmaxf(bi.x, bt.x);
            float y0 = fmaxf(bi.y, bt.y);
            float x1 = fminf(bi.z, bt.z);
            float y1 = fminf(bi.w, bt.w);
            float inter = fmaxf(x1 - x0, 0.0f) * fmaxf(y1 - y0, 0.0f);
            float area_i = fmaxf(bi.z - bi.x, 0.0f) * fmaxf(bi.w - bi.y, 0.0f);
            float iou = inter / fmaxf(area_i + area_t - inter, 1e-6f);
            if (t > i && iou > BOX_NMS_THRESH) sk[t] = 0;
            __syncthreads();
        }
    }

    // scatter back to original order, write keep + boxes tail, set gated
    int orig = si[t];
    int kept = sk[t];
    g_gated[orig] = kept ? iou_preds[orig] : 0.0f;
    if (out_size >= (long long)(TOTAL + NM)) {
        dout[TOTAL + orig] = kept ? 1.0f : 0.0f;
    }
    if (out_size >= (long long)(TOTAL + NM + 4 * NM)) {
        float4* boxout = reinterpret_cast<float4*>(dout + TOTAL + NM);
        boxout[orig] = g_boxes[orig];
    }
}

// ---------------------------------------------------------------------------
// Pass 2: out = sigmoid(logits) * gated. Non-kept masks (gated==0) are pure
// zero-fill stores — skip the load entirely.
// grid (4, 1024): 4 blocks x 256 threads x 16 float4 per mask.
// ---------------------------------------------------------------------------
__global__ void __launch_bounds__(256) output_kernel(const float* __restrict__ logits,
                                                     float* __restrict__ dout) {
    const int m = blockIdx.y;
    const float g = g_gated[m];
    const size_t base4 = (size_t)m * (HW / 4) + blockIdx.x * 4096;
    float4* o = reinterpret_cast<float4*>(dout) + base4;

    if (g == 0.0f) {
        float4 z = make_float4(0.f, 0.f, 0.f, 0.f);
#pragma unroll
        for (int it = 0; it < 16; ++it)
            o[it * 256 + threadIdx.x] = z;
    } else {
        const float4* in = reinterpret_cast<const float4*>(logits) + base4;
#pragma unroll
        for (int it = 0; it < 16; ++it) {
            float4 v = in[it * 256 + threadIdx.x];
            float4 r;
            r.x = g / (1.0f + expf(-v.x));
            r.y = g / (1.0f + expf(-v.y));
            r.z = g / (1.0f + expf(-v.z));
            r.w = g / (1.0f + expf(-v.w));
            o[it * 256 + threadIdx.x] = r;
        }
    }
}

extern "C" void kernel_launch(void* const* d_in, const int* in_sizes, int n_in,
                              void* d_out, int out_size) {
    const float* logits = (const float*)d_in[0];
    const float* iou    = (const float*)d_in[1];
    float* dout = (float*)d_out;

    stats_kernel<<<NM, 256>>>(logits, iou);
    nms_kernel<<<1, 1024>>>(iou, dout, (long long)out_size);
    output_kernel<<<dim3(4, NM), 256>>>(logits, dout);
}

// round 3
// speedup vs baseline: 1.6558x; 1.6558x over previous
#include <cuda_runtime.h>
#include <math.h>

#define NM 1024
#define H 256
#define W 256
#define HW (H * W)
#define TOTAL ((size_t)NM * HW)
#define CHUNKS 4                       // partial blocks per mask
#define NPART (NM * CHUNKS)

#define PRED_IOU_THRESH 0.88f
#define STABILITY_THRESH 0.95f
#define BOX_NMS_THRESH 0.7f

// Per-mask / per-partial scratch (allocation-free: __device__ globals)
__device__ int4   g_pA[NPART];   // hi, lo, minr, maxr
__device__ int2   g_pB[NPART];   // minc, maxc
__device__ float4 g_boxes[NM];   // xyxy inclusive, zeros if empty
__device__ float  g_gated[NM];   // iou_pred if kept else 0

// ---------------------------------------------------------------------------
// Pass 1: partial stats. 4 blocks per mask (64 rows each), 256 threads,
// 16 float4 per thread. Streaming loads. Every block rewrites its partial
// slot every launch (graph-replay safe, no reset needed).
// ---------------------------------------------------------------------------
__global__ void __launch_bounds__(256) stats_kernel(const float* __restrict__ logits) {
    const int blk = blockIdx.x;
    const int m = blk >> 2;
    const int chunk = blk & 3;
    const int tid = threadIdx.x;
    const float4* base = reinterpret_cast<const float4*>(logits)
                       + (size_t)m * (HW / 4) + chunk * 4096;

    int hi = 0, lo = 0;
    unsigned rowbits = 0;
    float cm0 = -1e30f, cm1 = -1e30f, cm2 = -1e30f, cm3 = -1e30f;

#pragma unroll
    for (int it = 0; it < 16; ++it) {
        float4 v = __ldcs(&base[it * 256 + tid]);
        hi += (v.x > 1.0f) + (v.y > 1.0f) + (v.z > 1.0f) + (v.w > 1.0f);
        lo += (v.x > -1.0f) + (v.y > -1.0f) + (v.z > -1.0f) + (v.w > -1.0f);
        cm0 = fmaxf(cm0, v.x);
        cm1 = fmaxf(cm1, v.y);
        cm2 = fmaxf(cm2, v.z);
        cm3 = fmaxf(cm3, v.w);
        float mx = fmaxf(fmaxf(v.x, v.y), fmaxf(v.z, v.w));
        if (mx > 0.0f) rowbits |= (1u << it);
    }

    // Thread-local bbox. This thread always touches columns col0..col0+3 and
    // rows chunk*64 + 4*it + (tid>>6).
    const int col0 = (tid * 4) & 255;
    int minc = W, maxc = -1;
    if (cm0 > 0.0f) { minc = col0;                 maxc = col0;     }
    if (cm1 > 0.0f) { minc = min(minc, col0 + 1);  maxc = col0 + 1; }
    if (cm2 > 0.0f) { minc = min(minc, col0 + 2);  maxc = col0 + 2; }
    if (cm3 > 0.0f) { minc = min(minc, col0 + 3);  maxc = col0 + 3; }
    int minr = H, maxr = -1;
    if (rowbits) {
        int rb = chunk * 64 + (tid >> 6);
        minr = rb + 4 * (__ffs(rowbits) - 1);
        maxr = rb + 4 * (31 - __clz(rowbits));
    }

    // warp reduce
#pragma unroll
    for (int off = 16; off > 0; off >>= 1) {
        hi   += __shfl_down_sync(0xffffffffu, hi, off);
        lo   += __shfl_down_sync(0xffffffffu, lo, off);
        minr = min(minr, __shfl_down_sync(0xffffffffu, minr, off));
        maxr = max(maxr, __shfl_down_sync(0xffffffffu, maxr, off));
        minc = min(minc, __shfl_down_sync(0xffffffffu, minc, off));
        maxc = max(maxc, __shfl_down_sync(0xffffffffu, maxc, off));
    }

    __shared__ int sh[8][6];
    int warp = tid >> 5;
    if ((tid & 31) == 0) {
        sh[warp][0] = hi;  sh[warp][1] = lo;
        sh[warp][2] = minr; sh[warp][3] = maxr;
        sh[warp][4] = minc; sh[warp][5] = maxc;
    }
    __syncthreads();
    if (tid == 0) {
#pragma unroll
        for (int wq = 1; wq < 8; ++wq) {
            hi += sh[wq][0]; lo += sh[wq][1];
            minr = min(minr, sh[wq][2]); maxr = max(maxr, sh[wq][3]);
            minc = min(minc, sh[wq][4]); maxc = max(maxc, sh[wq][5]);
        }
        g_pA[blk] = make_int4(hi, lo, minr, maxr);
        g_pB[blk] = make_int2(minc, maxc);
    }
}

// ---------------------------------------------------------------------------
// NMS: single block, 1024 threads. Merge partials -> validity/box, bitonic
// sort by (score desc, idx asc), then adjacency-bitmask suppression (fast
// path V<=256) or barrier'd greedy fallback. Writes keep + boxes tail.
// ---------------------------------------------------------------------------
__global__ void __launch_bounds__(1024) nms_kernel(const float* __restrict__ iou_preds,
                                                   float* __restrict__ dout,
                                                   long long out_size) {
    __shared__ float    ss[NM];
    __shared__ int      si[NM];
    __shared__ float4   sb[NM];
    __shared__ int      sk[NM];
    __shared__ unsigned adj[256][8];
    __shared__ unsigned removed_sh[8];
    __shared__ int      s_nv;

    const int t = threadIdx.x;

    // merge this mask's 4 partials
    int hi = 0, lo = 0, minr = H, maxr = -1, minc = W, maxc = -1;
#pragma unroll
    for (int c = 0; c < CHUNKS; ++c) {
        int4 a = g_pA[t * CHUNKS + c];
        int2 b = g_pB[t * CHUNKS + c];
        hi += a.x; lo += a.y;
        minr = min(minr, a.z); maxr = max(maxr, a.w);
        minc = min(minc, b.x); maxc = max(maxc, b.y);
    }
    float stability = (float)hi / fmaxf((float)lo, 1.0f);
    float iou_p = iou_preds[t];
    bool valid = (iou_p > PRED_IOU_THRESH) && (stability >= STABILITY_THRESH);
    float4 box = (maxr < 0) ? make_float4(0.f, 0.f, 0.f, 0.f)
                            : make_float4((float)minc, (float)minr, (float)maxc, (float)maxr);
    g_boxes[t] = box;

    ss[t] = valid ? iou_p : -INFINITY;
    si[t] = t;
    if (t == 0) s_nv = 0;
    __syncthreads();

    // bitonic sort: (score desc, idx asc)
    for (int k = 2; k <= NM; k <<= 1) {
        for (int j = k >> 1; j > 0; j >>= 1) {
            int ixj = t ^ j;
            if (ixj > t) {
                float sa = ss[t], sb_ = ss[ixj];
                int   ia = si[t], ib = si[ixj];
                bool less = (sa > sb_) || (sa == sb_ && ia < ib);
                bool dir = ((t & k) == 0);
                if (less != dir) {
                    ss[t] = sb_; ss[ixj] = sa;
                    si[t] = ib;  si[ixj] = ia;
                }
            }
            __syncthreads();
        }
    }

    sb[t] = g_boxes[si[t]];
    int keep0 = (ss[t] > -INFINITY) ? 1 : 0;
    sk[t] = keep0;
    if (keep0) atomicAdd(&s_nv, 1);
    if (t < 2048 - 1024) {}             // (no-op; adj zero below)
    // zero adjacency (2048 words, 1024 threads -> 2 each)
    reinterpret_cast<unsigned*>(adj)[t] = 0;
    reinterpret_cast<unsigned*>(adj)[t + 1024] = 0;
    __syncthreads();

    const int V = s_nv;
    const float4 bt = sb[t];
    const float area_t = fmaxf(bt.z - bt.x, 0.0f) * fmaxf(bt.w - bt.y, 0.0f);

    if (V <= 256) {
        // build adjacency: bit (row i, col t) set iff i<t and iou>thresh
        if (t < V) {
            for (int i = 0; i < t; ++i) {
                float4 bi = sb[i];
                float x0 = fmaxf(bi.x, bt.x);
                float y0 = fmaxf(bi.y, bt.y);
                float x1 = fminf(bi.z, bt.z);
                float y1 = fminf(bi.w, bt.w);
                float inter = fmaxf(x1 - x0, 0.0f) * fmaxf(y1 - y0, 0.0f);
                float area_i = fmaxf(bi.z - bi.x, 0.0f) * fmaxf(bi.w - bi.y, 0.0f);
                float iou = inter / fmaxf(area_i + area_t - inter, 1e-6f);
                if (iou > BOX_NMS_THRESH)
                    atomicOr(&adj[i][t >> 5], 1u << (t & 31));
            }
        }
        __syncthreads();
        if (t == 0) {
            unsigned removed[8] = {0, 0, 0, 0, 0, 0, 0, 0};
            int nw = (V + 31) >> 5;
            for (int i = 0; i < V; ++i) {
                if (!((removed[i >> 5] >> (i & 31)) & 1u)) {
                    for (int w = 0; w < nw; ++w) removed[w] |= adj[i][w];
                }
            }
#pragma unroll
            for (int w = 0; w < 8; ++w) removed_sh[w] = removed[w];
        }
        __syncthreads();
        sk[t] = (t < V) && !((removed_sh[t >> 5] >> (t & 31)) & 1u);
    } else {
        // fallback: exact barrier'd greedy
        for (int i = 0; i < V; ++i) {
            if (sk[i]) {
                float4 bi = sb[i];
                float x0 = fmaxf(bi.x, bt.x);
                float y0 = fmaxf(bi.y, bt.y);
                float x1 = fminf(bi.z, bt.z);
                float y1 = fminf(bi.w, bt.w);
                float inter = fmaxf(x1 - x0, 0.0f) * fmaxf(y1 - y0, 0.0f);
                float area_i = fmaxf(bi.z - bi.x, 0.0f) * fmaxf(bi.w - bi.y, 0.0f);
                float iou = inter / fmaxf(area_i + area_t - inter, 1e-6f);
                if (t > i && iou > BOX_NMS_THRESH) sk[t] = 0;
            }
            __syncthreads();
        }
    }

    // scatter to original order, write keep + boxes tail, set gated
    int orig = si[t];
    int kept = sk[t];
    g_gated[orig] = kept ? iou_preds[orig] : 0.0f;
    if (out_size >= (long long)(TOTAL + NM)) {
        dout[TOTAL + orig] = kept ? 1.0f : 0.0f;
    }
    if (out_size >= (long long)(TOTAL + NM + 4 * NM)) {
        float4* boxout = reinterpret_cast<float4*>(dout + TOTAL + NM);
        boxout[orig] = g_boxes[orig];
    }
}

// ---------------------------------------------------------------------------
// Pass 2: out = sigmoid(logits) * gated, streaming stores. Non-kept masks
// are pure zero-fill. grid (8, 1024): 8 blocks x 256 threads x 8 float4.
// ---------------------------------------------------------------------------
__global__ void __launch_bounds__(256) output_kernel(const float* __restrict__ logits,
                                                     float* __restrict__ dout) {
    const int m = blockIdx.y;
    const float g = g_gated[m];
    const size_t base4 = (size_t)m * (HW / 4) + blockIdx.x * 2048;
    float4* o = reinterpret_cast<float4*>(dout) + base4;

    if (g == 0.0f) {
        float4 z = make_float4(0.f, 0.f, 0.f, 0.f);
#pragma unroll
        for (int it = 0; it < 8; ++it)
            __stcs(&o[it * 256 + threadIdx.x], z);
    } else {
        const float4* in = reinterpret_cast<const float4*>(logits) + base4;
#pragma unroll
        for (int it = 0; it < 8; ++it) {
            float4 v = __ldcs(&in[it * 256 + threadIdx.x]);
            float4 r;
            r.x = g / (1.0f + __expf(-v.x));
            r.y = g / (1.0f + __expf(-v.y));
            r.z = g / (1.0f + __expf(-v.z));
            r.w = g / (1.0f + __expf(-v.w));
            __stcs(&o[it * 256 + threadIdx.x], r);
        }
    }
}

extern "C" void kernel_launch(void* const* d_in, const int* in_sizes, int n_in,
                              void* d_out, int out_size) {
    const float* logits = (const float*)d_in[0];
    const float* iou    = (const float*)d_in[1];
    float* dout = (float*)d_out;

    stats_kernel<<<NPART, 256>>>(logits);
    nms_kernel<<<1, 1024>>>(iou, dout, (long long)out_size);
    output_kernel<<<dim3(8, NM), 256>>>(logits, dout);
}